// round 3
// baseline (speedup 1.0000x reference)
#include <cuda_runtime.h>
#include <math.h>

#define NN 100000
#define NE 1600000

// ---------------- scratch (device globals: no runtime allocation) ----------
__device__ int   g_is64;
__device__ int   g_deg[NN];
__device__ int   g_rowptr[NN + 1];
__device__ int   g_cursor[NN];
__device__ int   g_csrsrc[NE];
__device__ float g_mean[(size_t)NN * 128];  // reused: mean1 then mean2
__device__ float g_h[(size_t)NN * 128];     // relu(layer1) output

// ---------------- edge dtype probe -----------------------------------------
// JAX with x64 disabled silently downcasts int64 -> int32, so the edge buffer
// may be either. Interpreting int32 pairs as int64 gives values ~src+dst*2^32,
// far outside [0, NN); real int64 data lands inside. Probe once per launch.
__global__ void k_probe(const void* __restrict__ ei) {
    if (threadIdx.x == 0 && blockIdx.x == 0) {
        const long long* e64 = (const long long*)ei;
        int ok = 1;
        for (int i = 0; i < 1024; i++) {
            long long v = e64[i];
            if (v < 0 || v >= NN) { ok = 0; break; }
        }
        g_is64 = ok;
    }
}

__device__ __forceinline__ int edge_at(const void* ei, int idx) {
    if (g_is64) return (int)((const long long*)ei)[idx];
    return ((const int*)ei)[idx];
}

// ---------------- CSR build ------------------------------------------------
__global__ void k_zero_deg() {
    int i = blockIdx.x * 256 + threadIdx.x;
    if (i < NN) g_deg[i] = 0;
}

__global__ void k_count_deg(const void* __restrict__ ei) {
    int e = blockIdx.x * 256 + threadIdx.x;
    if (e < NE) {
        int dst = edge_at(ei, NE + e);
        if ((unsigned)dst < NN) atomicAdd(&g_deg[dst], 1);
    }
}

__global__ void k_scan() {
    __shared__ int sums[1024];
    int tid = threadIdx.x;
    const int CH = (NN + 1023) / 1024;  // 98
    int base = tid * CH;
    int s = 0;
    for (int i = 0; i < CH; i++) {
        int idx = base + i;
        if (idx < NN) s += g_deg[idx];
    }
    sums[tid] = s;
    __syncthreads();
    for (int off = 1; off < 1024; off <<= 1) {
        int v = 0;
        if (tid >= off) v = sums[tid - off];
        __syncthreads();
        if (tid >= off) sums[tid] += v;
        __syncthreads();
    }
    int run = (tid > 0) ? sums[tid - 1] : 0;
    for (int i = 0; i < CH; i++) {
        int idx = base + i;
        if (idx < NN) {
            g_rowptr[idx] = run;
            g_cursor[idx] = run;
            run += g_deg[idx];
        }
    }
    if (tid == 1023) g_rowptr[NN] = sums[1023];
}

__global__ void k_scatter(const void* __restrict__ ei) {
    int e = blockIdx.x * 256 + threadIdx.x;
    if (e < NE) {
        int src = edge_at(ei, e);
        int dst = edge_at(ei, NE + e);
        if ((unsigned)dst < NN && (unsigned)src < NN) {
            int pos = atomicAdd(&g_cursor[dst], 1);
            if ((unsigned)pos < NE) g_csrsrc[pos] = src;
        }
    }
}

// ---------------- mean aggregation: one warp per node ----------------------
__device__ __forceinline__ void agg_body(const float* __restrict__ in,
                                         float* __restrict__ out) {
    int w = (blockIdx.x * blockDim.x + threadIdx.x) >> 5;
    int lane = threadIdx.x & 31;
    if (w >= NN) return;
    int s = g_rowptr[w], e = g_rowptr[w + 1];
    float4 acc = make_float4(0.f, 0.f, 0.f, 0.f);
    const float4* in4 = (const float4*)in;
    int i = s;
    for (; i + 1 < e; i += 2) {
        int s0 = g_csrsrc[i];
        int s1 = g_csrsrc[i + 1];
        float4 v0 = in4[(size_t)s0 * 32 + lane];
        float4 v1 = in4[(size_t)s1 * 32 + lane];
        acc.x += v0.x + v1.x;
        acc.y += v0.y + v1.y;
        acc.z += v0.z + v1.z;
        acc.w += v0.w + v1.w;
    }
    if (i < e) {
        int s0 = g_csrsrc[i];
        float4 v0 = in4[(size_t)s0 * 32 + lane];
        acc.x += v0.x; acc.y += v0.y; acc.z += v0.z; acc.w += v0.w;
    }
    float inv = (e > s) ? 1.0f / (float)(e - s) : 1.0f;
    acc.x *= inv; acc.y *= inv; acc.z *= inv; acc.w *= inv;
    ((float4*)out)[(size_t)w * 32 + lane] = acc;
}

__global__ void k_agg_x(const float* __restrict__ x) { agg_body(x, g_mean); }
__global__ void k_agg_h() { agg_body(g_h, g_mean); }

// ---------------- layer 1: h = relu([mean|x] @ [W1l|W1r]^T + b1) -----------
// BM=128, BN=128, BK=16, 256 threads, 8x8 register tile. Static smem 16.25KB.
__global__ __launch_bounds__(256) void k_gemm1(const float* __restrict__ x,
                                               const float* __restrict__ W1l,
                                               const float* __restrict__ b1,
                                               const float* __restrict__ W1r) {
    __shared__ float sA[16][128];   // [k][m]
    __shared__ float sB[16][132];   // [k][n], padded
    int tid = threadIdx.x;
    int rowbase = blockIdx.x * 128;
    int tm = tid >> 4, tn = tid & 15;

    float acc[8][8];
#pragma unroll
    for (int i = 0; i < 8; i++)
#pragma unroll
        for (int j = 0; j < 8; j++) acc[i][j] = 0.f;

    for (int step = 0; step < 16; step++) {
        int k0 = step * 16;
        const float* Asrc = (k0 < 128) ? g_mean : x;
        const float* Wsrc = (k0 < 128) ? W1l : W1r;
        int kb = k0 & 127;
        __syncthreads();
#pragma unroll
        for (int q = tid; q < 512; q += 256) {
            int m = q >> 2, kq = (q & 3) * 4;
            float4 v = make_float4(0.f, 0.f, 0.f, 0.f);
            int row = rowbase + m;
            if (row < NN) v = *(const float4*)&Asrc[(size_t)row * 128 + kb + kq];
            sA[kq + 0][m] = v.x;
            sA[kq + 1][m] = v.y;
            sA[kq + 2][m] = v.z;
            sA[kq + 3][m] = v.w;
            float4 w = *(const float4*)&Wsrc[(size_t)m * 128 + kb + kq];
            sB[kq + 0][m] = w.x;
            sB[kq + 1][m] = w.y;
            sB[kq + 2][m] = w.z;
            sB[kq + 3][m] = w.w;
        }
        __syncthreads();
#pragma unroll
        for (int kk = 0; kk < 16; kk++) {
            float a[8], b[8];
            *(float4*)&a[0] = *(const float4*)&sA[kk][tm * 8];
            *(float4*)&a[4] = *(const float4*)&sA[kk][tm * 8 + 4];
            *(float4*)&b[0] = *(const float4*)&sB[kk][tn * 8];
            *(float4*)&b[4] = *(const float4*)&sB[kk][tn * 8 + 4];
#pragma unroll
            for (int i = 0; i < 8; i++)
#pragma unroll
                for (int j = 0; j < 8; j++) acc[i][j] += a[i] * b[j];
        }
    }

    float bias[8];
    *(float4*)&bias[0] = *(const float4*)&b1[tn * 8];
    *(float4*)&bias[4] = *(const float4*)&b1[tn * 8 + 4];
#pragma unroll
    for (int i = 0; i < 8; i++) {
        int row = rowbase + tm * 8 + i;
        if (row < NN) {
            float4 o1, o2;
            o1.x = fmaxf(acc[i][0] + bias[0], 0.f);
            o1.y = fmaxf(acc[i][1] + bias[1], 0.f);
            o1.z = fmaxf(acc[i][2] + bias[2], 0.f);
            o1.w = fmaxf(acc[i][3] + bias[3], 0.f);
            o2.x = fmaxf(acc[i][4] + bias[4], 0.f);
            o2.y = fmaxf(acc[i][5] + bias[5], 0.f);
            o2.z = fmaxf(acc[i][6] + bias[6], 0.f);
            o2.w = fmaxf(acc[i][7] + bias[7], 0.f);
            *(float4*)&g_h[(size_t)row * 128 + tn * 8] = o1;
            *(float4*)&g_h[(size_t)row * 128 + tn * 8 + 4] = o2;
        }
    }
}

// ---------------- layer 2 + log_softmax ------------------------------------
// BM=128, BN=64(all classes), BK=16, 256 threads, 8x4 register tile.
// Shared buffer reused: mainloop tiles then the 128x65 C tile. 33.3KB static.
__global__ __launch_bounds__(256) void k_gemm2(const float* __restrict__ W2l,
                                               const float* __restrict__ b2,
                                               const float* __restrict__ W2r,
                                               float* __restrict__ out) {
    __shared__ float sbuf[128 * 65];   // >= 16*128 + 16*68
    __shared__ float sLZ[128];
    float (*sA)[128] = (float (*)[128])sbuf;            // [16][128]
    float (*sB)[68]  = (float (*)[68])(sbuf + 2048);    // [16][68]
    int tid = threadIdx.x;
    int rowbase = blockIdx.x * 128;
    int tm = tid >> 4, tn = tid & 15;

    float acc[8][4];
#pragma unroll
    for (int i = 0; i < 8; i++)
#pragma unroll
        for (int j = 0; j < 4; j++) acc[i][j] = 0.f;

    for (int step = 0; step < 16; step++) {
        int k0 = step * 16;
        const float* Asrc = (k0 < 128) ? g_mean : g_h;
        const float* Wsrc = (k0 < 128) ? W2l : W2r;
        int kb = k0 & 127;
        __syncthreads();
        // A tile: 2048 elems
#pragma unroll
        for (int q = tid; q < 512; q += 256) {
            int m = q >> 2, kq = (q & 3) * 4;
            float4 v = make_float4(0.f, 0.f, 0.f, 0.f);
            int row = rowbase + m;
            if (row < NN) v = *(const float4*)&Asrc[(size_t)row * 128 + kb + kq];
            sA[kq + 0][m] = v.x;
            sA[kq + 1][m] = v.y;
            sA[kq + 2][m] = v.z;
            sA[kq + 3][m] = v.w;
        }
        // B tile: 64 rows x 16 k = 1024 elems = 256 float4
        {
            int q = tid;
            int n = q >> 2, kq = (q & 3) * 4;
            float4 w = *(const float4*)&Wsrc[(size_t)n * 128 + kb + kq];
            sB[kq + 0][n] = w.x;
            sB[kq + 1][n] = w.y;
            sB[kq + 2][n] = w.z;
            sB[kq + 3][n] = w.w;
        }
        __syncthreads();
#pragma unroll
        for (int kk = 0; kk < 16; kk++) {
            float a[8], b[4];
            *(float4*)&a[0] = *(const float4*)&sA[kk][tm * 8];
            *(float4*)&a[4] = *(const float4*)&sA[kk][tm * 8 + 4];
            *(float4*)&b[0] = *(const float4*)&sB[kk][tn * 4];
#pragma unroll
            for (int i = 0; i < 8; i++)
#pragma unroll
                for (int j = 0; j < 4; j++) acc[i][j] += a[i] * b[j];
        }
    }
    __syncthreads();  // everyone done reading tiles; reuse sbuf as C

    float (*sC)[65] = (float (*)[65])sbuf;  // [128][65]
    float bz[4];
    *(float4*)&bz[0] = *(const float4*)&b2[tn * 4];
#pragma unroll
    for (int i = 0; i < 8; i++)
#pragma unroll
        for (int j = 0; j < 4; j++)
            sC[tm * 8 + i][tn * 4 + j] = acc[i][j] + bz[j];
    __syncthreads();

    if (tid < 128) {
        float m = -INFINITY;
#pragma unroll
        for (int c = 0; c < 64; c++) m = fmaxf(m, sC[tid][c]);
        float s = 0.f;
#pragma unroll
        for (int c = 0; c < 64; c++) s += __expf(sC[tid][c] - m);
        sLZ[tid] = m + __logf(s);
    }
    __syncthreads();

#pragma unroll
    for (int q = tid; q < 8192; q += 256) {
        int r = q >> 6, c = q & 63;
        int row = rowbase + r;
        if (row < NN) out[(size_t)row * 64 + c] = sC[r][c] - sLZ[r];
    }
}

// ---------------- launch ---------------------------------------------------
extern "C" void kernel_launch(void* const* d_in, const int* in_sizes, int n_in,
                              void* d_out, int out_size) {
    const float* x   = (const float*)d_in[0];
    const void*  ei  = d_in[1];
    const float* W1l = (const float*)d_in[2];
    const float* b1  = (const float*)d_in[3];
    const float* W1r = (const float*)d_in[4];
    const float* W2l = (const float*)d_in[5];
    const float* b2  = (const float*)d_in[6];
    const float* W2r = (const float*)d_in[7];
    float* out = (float*)d_out;
    (void)in_sizes; (void)n_in; (void)out_size;

    // edge dtype probe + CSR build
    k_probe<<<1, 32>>>(ei);
    k_zero_deg<<<(NN + 255) / 256, 256>>>();
    k_count_deg<<<(NE + 255) / 256, 256>>>(ei);
    k_scan<<<1, 1024>>>();
    k_scatter<<<(NE + 255) / 256, 256>>>(ei);

    // layer 1
    k_agg_x<<<12500, 256>>>(x);                           // mean1 -> g_mean
    k_gemm1<<<(NN + 127) / 128, 256>>>(x, W1l, b1, W1r);  // -> g_h

    // layer 2
    k_agg_h<<<12500, 256>>>();                            // mean2 -> g_mean
    k_gemm2<<<(NN + 127) / 128, 256>>>(W2l, b2, W2r, out);
}

// round 5
// speedup vs baseline: 1.3607x; 1.3607x over previous
// R5: re-bench of R4 (container infra failure, kernel unmeasured)
#include <cuda_runtime.h>
#include <math.h>

#define NN 100000
#define NE 1600000
#define NBLK 98            // ceil(NN / 1024)

// ---------------- scratch (device globals: no runtime allocation) ----------
__device__ int   g_is64;
__device__ int   g_deg[NN + 4];      // pad so int4 loads at tail are safe
__device__ int   g_rowptr[NN + 1];
__device__ int   g_cursor[NN];
__device__ int   g_csrsrc[NE];
__device__ int   g_bsum[NBLK];
__device__ int   g_boff[NBLK];
__device__ float g_mean[(size_t)NN * 128];  // reused: mean1 then mean2
__device__ float g_h[(size_t)NN * 128];     // relu(layer1) output

// ---------------- edge dtype probe -----------------------------------------
// JAX with x64 disabled silently downcasts int64 -> int32, so the edge buffer
// may be either width. int32 pairs read as int64 produce values far outside
// [0, NN); genuine int64 data lands inside. Probe once per launch.
__global__ void k_probe(const void* __restrict__ ei) {
    if (threadIdx.x == 0 && blockIdx.x == 0) {
        const long long* e64 = (const long long*)ei;
        int ok = 1;
        for (int i = 0; i < 1024; i++) {
            long long v = e64[i];
            if (v < 0 || v >= NN) { ok = 0; break; }
        }
        g_is64 = ok;
    }
}

__device__ __forceinline__ int edge_at(const void* ei, int idx) {
    if (g_is64) return (int)((const long long*)ei)[idx];
    return ((const int*)ei)[idx];
}

// ---------------- CSR build ------------------------------------------------
__global__ void k_zero_deg() {
    int i = blockIdx.x * 256 + threadIdx.x;   // NN/4 = 25000 int4 stores
    if (i * 4 < NN) *(int4*)&g_deg[i * 4] = make_int4(0, 0, 0, 0);
}

__global__ void k_count_deg(const void* __restrict__ ei) {
    int e = blockIdx.x * 256 + threadIdx.x;
    if (e < NE) {
        int dst = edge_at(ei, NE + e);
        if ((unsigned)dst < NN) atomicAdd(&g_deg[dst], 1);
    }
}

// -- parallel scan: partial sums -> top scan -> per-block rowptr -------------
__global__ void k_partial() {
    __shared__ int wsum[8];
    int b = blockIdx.x, tid = threadIdx.x;
    int idx = b * 1024 + tid * 4;
    int s = 0;
    if (idx < NN) {                       // g_deg padded: int4 always safe
        int4 d = *(const int4*)&g_deg[idx];
        s = ((idx + 0 < NN) ? d.x : 0) + ((idx + 1 < NN) ? d.y : 0) +
            ((idx + 2 < NN) ? d.z : 0) + ((idx + 3 < NN) ? d.w : 0);
    }
    int lane = tid & 31, wid = tid >> 5;
#pragma unroll
    for (int off = 16; off > 0; off >>= 1) s += __shfl_down_sync(0xffffffffu, s, off);
    if (lane == 0) wsum[wid] = s;
    __syncthreads();
    if (tid == 0) {
        int t = 0;
#pragma unroll
        for (int i = 0; i < 8; i++) t += wsum[i];
        g_bsum[b] = t;
    }
}

__global__ void k_scan_top() {
    __shared__ int ws[4];
    int tid = threadIdx.x;                   // 128 threads
    int v = (tid < NBLK) ? g_bsum[tid] : 0;
    int lane = tid & 31, wid = tid >> 5;
    int incl = v;
#pragma unroll
    for (int off = 1; off < 32; off <<= 1) {
        int n = __shfl_up_sync(0xffffffffu, incl, off);
        if (lane >= off) incl += n;
    }
    if (lane == 31) ws[wid] = incl;
    __syncthreads();
    if (tid < 4) {
        int t = ws[tid];
#pragma unroll
        for (int off = 1; off < 4; off <<= 1) {
            int n = __shfl_up_sync(0xfu, t, off);
            if (tid >= off) t += n;
        }
        ws[tid] = t;
    }
    __syncthreads();
    int excl = incl - v + ((wid > 0) ? ws[wid - 1] : 0);
    if (tid < NBLK) g_boff[tid] = excl;
    if (tid == NBLK - 1) g_rowptr[NN] = excl + v;
}

__global__ void k_rowptr() {
    __shared__ int wsum[8];
    int b = blockIdx.x, tid = threadIdx.x;
    int idx = b * 1024 + tid * 4;
    int d0 = 0, d1 = 0, d2 = 0, d3 = 0;
    if (idx < NN) {
        int4 d = *(const int4*)&g_deg[idx];
        d0 = (idx + 0 < NN) ? d.x : 0;
        d1 = (idx + 1 < NN) ? d.y : 0;
        d2 = (idx + 2 < NN) ? d.z : 0;
        d3 = (idx + 3 < NN) ? d.w : 0;
    }
    int s = d0 + d1 + d2 + d3;
    int lane = tid & 31, wid = tid >> 5;
    int incl = s;
#pragma unroll
    for (int off = 1; off < 32; off <<= 1) {
        int n = __shfl_up_sync(0xffffffffu, incl, off);
        if (lane >= off) incl += n;
    }
    if (lane == 31) wsum[wid] = incl;
    __syncthreads();
    if (tid < 8) {
        int t = wsum[tid];
#pragma unroll
        for (int off = 1; off < 8; off <<= 1) {
            int n = __shfl_up_sync(0xffu, t, off);
            if (tid >= off) t += n;
        }
        wsum[tid] = t;
    }
    __syncthreads();
    int run = incl - s + ((wid > 0) ? wsum[wid - 1] : 0) + g_boff[b];
    if (idx + 0 < NN) { g_rowptr[idx + 0] = run; g_cursor[idx + 0] = run; run += d0; }
    if (idx + 1 < NN) { g_rowptr[idx + 1] = run; g_cursor[idx + 1] = run; run += d1; }
    if (idx + 2 < NN) { g_rowptr[idx + 2] = run; g_cursor[idx + 2] = run; run += d2; }
    if (idx + 3 < NN) { g_rowptr[idx + 3] = run; g_cursor[idx + 3] = run; run += d3; }
}

__global__ void k_scatter(const void* __restrict__ ei) {
    int e = blockIdx.x * 256 + threadIdx.x;
    if (e < NE) {
        int src = edge_at(ei, e);
        int dst = edge_at(ei, NE + e);
        if ((unsigned)dst < NN && (unsigned)src < NN) {
            int pos = atomicAdd(&g_cursor[dst], 1);
            if ((unsigned)pos < NE) g_csrsrc[pos] = src;
        }
    }
}

// ---------------- mean aggregation: one warp per node ----------------------
__device__ __forceinline__ void agg_body(const float* __restrict__ in,
                                         float* __restrict__ out) {
    int w = (blockIdx.x * blockDim.x + threadIdx.x) >> 5;
    int lane = threadIdx.x & 31;
    if (w >= NN) return;
    int s = g_rowptr[w], e = g_rowptr[w + 1];
    float4 acc = make_float4(0.f, 0.f, 0.f, 0.f);
    const float4* in4 = (const float4*)in;
    int i = s;
    for (; i + 1 < e; i += 2) {
        int s0 = g_csrsrc[i];
        int s1 = g_csrsrc[i + 1];
        float4 v0 = in4[(size_t)s0 * 32 + lane];
        float4 v1 = in4[(size_t)s1 * 32 + lane];
        acc.x += v0.x + v1.x;
        acc.y += v0.y + v1.y;
        acc.z += v0.z + v1.z;
        acc.w += v0.w + v1.w;
    }
    if (i < e) {
        int s0 = g_csrsrc[i];
        float4 v0 = in4[(size_t)s0 * 32 + lane];
        acc.x += v0.x; acc.y += v0.y; acc.z += v0.z; acc.w += v0.w;
    }
    float inv = (e > s) ? 1.0f / (float)(e - s) : 1.0f;
    acc.x *= inv; acc.y *= inv; acc.z *= inv; acc.w *= inv;
    ((float4*)out)[(size_t)w * 32 + lane] = acc;
}

__global__ void k_agg_x(const float* __restrict__ x) { agg_body(x, g_mean); }
__global__ void k_agg_h() { agg_body(g_h, g_mean); }

// ---------------- layer 1: h = relu([mean|x] @ [W1l|W1r]^T + b1) -----------
// BM=128, BN=128, BK=16, 256 threads, 8x8 register tile. Static smem 16.25KB.
__global__ __launch_bounds__(256) void k_gemm1(const float* __restrict__ x,
                                               const float* __restrict__ W1l,
                                               const float* __restrict__ b1,
                                               const float* __restrict__ W1r) {
    __shared__ float sA[16][128];   // [k][m]
    __shared__ float sB[16][132];   // [k][n], padded
    int tid = threadIdx.x;
    int rowbase = blockIdx.x * 128;
    int tm = tid >> 4, tn = tid & 15;

    float acc[8][8];
#pragma unroll
    for (int i = 0; i < 8; i++)
#pragma unroll
        for (int j = 0; j < 8; j++) acc[i][j] = 0.f;

    for (int step = 0; step < 16; step++) {
        int k0 = step * 16;
        const float* Asrc = (k0 < 128) ? g_mean : x;
        const float* Wsrc = (k0 < 128) ? W1l : W1r;
        int kb = k0 & 127;
        __syncthreads();
#pragma unroll
        for (int q = tid; q < 512; q += 256) {
            int m = q >> 2, kq = (q & 3) * 4;
            float4 v = make_float4(0.f, 0.f, 0.f, 0.f);
            int row = rowbase + m;
            if (row < NN) v = *(const float4*)&Asrc[(size_t)row * 128 + kb + kq];
            sA[kq + 0][m] = v.x;
            sA[kq + 1][m] = v.y;
            sA[kq + 2][m] = v.z;
            sA[kq + 3][m] = v.w;
            float4 w = *(const float4*)&Wsrc[(size_t)m * 128 + kb + kq];
            sB[kq + 0][m] = w.x;
            sB[kq + 1][m] = w.y;
            sB[kq + 2][m] = w.z;
            sB[kq + 3][m] = w.w;
        }
        __syncthreads();
#pragma unroll
        for (int kk = 0; kk < 16; kk++) {
            float a[8], b[8];
            *(float4*)&a[0] = *(const float4*)&sA[kk][tm * 8];
            *(float4*)&a[4] = *(const float4*)&sA[kk][tm * 8 + 4];
            *(float4*)&b[0] = *(const float4*)&sB[kk][tn * 8];
            *(float4*)&b[4] = *(const float4*)&sB[kk][tn * 8 + 4];
#pragma unroll
            for (int i = 0; i < 8; i++)
#pragma unroll
                for (int j = 0; j < 8; j++) acc[i][j] += a[i] * b[j];
        }
    }

    float bias[8];
    *(float4*)&bias[0] = *(const float4*)&b1[tn * 8];
    *(float4*)&bias[4] = *(const float4*)&b1[tn * 8 + 4];
#pragma unroll
    for (int i = 0; i < 8; i++) {
        int row = rowbase + tm * 8 + i;
        if (row < NN) {
            float4 o1, o2;
            o1.x = fmaxf(acc[i][0] + bias[0], 0.f);
            o1.y = fmaxf(acc[i][1] + bias[1], 0.f);
            o1.z = fmaxf(acc[i][2] + bias[2], 0.f);
            o1.w = fmaxf(acc[i][3] + bias[3], 0.f);
            o2.x = fmaxf(acc[i][4] + bias[4], 0.f);
            o2.y = fmaxf(acc[i][5] + bias[5], 0.f);
            o2.z = fmaxf(acc[i][6] + bias[6], 0.f);
            o2.w = fmaxf(acc[i][7] + bias[7], 0.f);
            *(float4*)&g_h[(size_t)row * 128 + tn * 8] = o1;
            *(float4*)&g_h[(size_t)row * 128 + tn * 8 + 4] = o2;
        }
    }
}

// ---------------- layer 2 + log_softmax ------------------------------------
// BM=128, BN=64(all classes), BK=16, 256 threads, 8x4 register tile.
// Shared buffer reused: mainloop tiles then the 128x65 C tile. 33.3KB static.
__global__ __launch_bounds__(256) void k_gemm2(const float* __restrict__ W2l,
                                               const float* __restrict__ b2,
                                               const float* __restrict__ W2r,
                                               float* __restrict__ out) {
    __shared__ float sbuf[128 * 65];   // >= 16*128 + 16*68
    __shared__ float sLZ[128];
    float (*sA)[128] = (float (*)[128])sbuf;            // [16][128]
    float (*sB)[68]  = (float (*)[68])(sbuf + 2048);    // [16][68]
    int tid = threadIdx.x;
    int rowbase = blockIdx.x * 128;
    int tm = tid >> 4, tn = tid & 15;

    float acc[8][4];
#pragma unroll
    for (int i = 0; i < 8; i++)
#pragma unroll
        for (int j = 0; j < 4; j++) acc[i][j] = 0.f;

    for (int step = 0; step < 16; step++) {
        int k0 = step * 16;
        const float* Asrc = (k0 < 128) ? g_mean : g_h;
        const float* Wsrc = (k0 < 128) ? W2l : W2r;
        int kb = k0 & 127;
        __syncthreads();
        // A tile: 2048 elems
#pragma unroll
        for (int q = tid; q < 512; q += 256) {
            int m = q >> 2, kq = (q & 3) * 4;
            float4 v = make_float4(0.f, 0.f, 0.f, 0.f);
            int row = rowbase + m;
            if (row < NN) v = *(const float4*)&Asrc[(size_t)row * 128 + kb + kq];
            sA[kq + 0][m] = v.x;
            sA[kq + 1][m] = v.y;
            sA[kq + 2][m] = v.z;
            sA[kq + 3][m] = v.w;
        }
        // B tile: 64 rows x 16 k = 1024 elems = 256 float4
        {
            int q = tid;
            int n = q >> 2, kq = (q & 3) * 4;
            float4 w = *(const float4*)&Wsrc[(size_t)n * 128 + kb + kq];
            sB[kq + 0][n] = w.x;
            sB[kq + 1][n] = w.y;
            sB[kq + 2][n] = w.z;
            sB[kq + 3][n] = w.w;
        }
        __syncthreads();
#pragma unroll
        for (int kk = 0; kk < 16; kk++) {
            float a[8], b[4];
            *(float4*)&a[0] = *(const float4*)&sA[kk][tm * 8];
            *(float4*)&a[4] = *(const float4*)&sA[kk][tm * 8 + 4];
            *(float4*)&b[0] = *(const float4*)&sB[kk][tn * 4];
#pragma unroll
            for (int i = 0; i < 8; i++)
#pragma unroll
                for (int j = 0; j < 4; j++) acc[i][j] += a[i] * b[j];
        }
    }
    __syncthreads();  // everyone done reading tiles; reuse sbuf as C

    float (*sC)[65] = (float (*)[65])sbuf;  // [128][65]
    float bz[4];
    *(float4*)&bz[0] = *(const float4*)&b2[tn * 4];
#pragma unroll
    for (int i = 0; i < 8; i++)
#pragma unroll
        for (int j = 0; j < 4; j++)
            sC[tm * 8 + i][tn * 4 + j] = acc[i][j] + bz[j];
    __syncthreads();

    if (tid < 128) {
        float m = -INFINITY;
#pragma unroll
        for (int c = 0; c < 64; c++) m = fmaxf(m, sC[tid][c]);
        float s = 0.f;
#pragma unroll
        for (int c = 0; c < 64; c++) s += __expf(sC[tid][c] - m);
        sLZ[tid] = m + __logf(s);
    }
    __syncthreads();

#pragma unroll
    for (int q = tid; q < 8192; q += 256) {
        int r = q >> 6, c = q & 63;
        int row = rowbase + r;
        if (row < NN) out[(size_t)row * 64 + c] = sC[r][c] - sLZ[r];
    }
}

// ---------------- launch ---------------------------------------------------
extern "C" void kernel_launch(void* const* d_in, const int* in_sizes, int n_in,
                              void* d_out, int out_size) {
    const float* x   = (const float*)d_in[0];
    const void*  ei  = d_in[1];
    const float* W1l = (const float*)d_in[2];
    const float* b1  = (const float*)d_in[3];
    const float* W1r = (const float*)d_in[4];
    const float* W2l = (const float*)d_in[5];
    const float* b2  = (const float*)d_in[6];
    const float* W2r = (const float*)d_in[7];
    float* out = (float*)d_out;
    (void)in_sizes; (void)n_in; (void)out_size;

    // edge dtype probe + CSR build (parallel 3-stage scan)
    k_probe<<<1, 32>>>(ei);
    k_zero_deg<<<(NN / 4 + 255) / 256, 256>>>();
    k_count_deg<<<(NE + 255) / 256, 256>>>(ei);
    k_partial<<<NBLK, 256>>>();
    k_scan_top<<<1, 128>>>();
    k_rowptr<<<NBLK, 256>>>();
    k_scatter<<<(NE + 255) / 256, 256>>>(ei);

    // layer 1
    k_agg_x<<<12500, 256>>>(x);                           // mean1 -> g_mean
    k_gemm1<<<(NN + 127) / 128, 256>>>(x, W1l, b1, W1r);  // -> g_h

    // layer 2
    k_agg_h<<<12500, 256>>>();                            // mean2 -> g_mean
    k_gemm2<<<(NN + 127) / 128, 256>>>(W2l, b2, W2r, out);
}

// round 7
// speedup vs baseline: 1.4669x; 1.0781x over previous
// R7: re-bench of R6 TF32 mma.sync kernels (container infra failure, unmeasured)
#include <cuda_runtime.h>
#include <math.h>
#include <stdint.h>

#define NN 100000
#define NE 1600000
#define NBLK 98            // ceil(NN / 1024)

// ---------------- scratch (device globals: no runtime allocation) ----------
__device__ int   g_is64;
__device__ int   g_deg[NN + 4];      // pad so int4 loads at tail are safe
__device__ int   g_rowptr[NN + 1];
__device__ int   g_cursor[NN];
__device__ int   g_csrsrc[NE];
__device__ int   g_bsum[NBLK];
__device__ int   g_boff[NBLK];
__device__ float g_mean[(size_t)NN * 128];  // reused: mean1 then mean2
__device__ float g_h[(size_t)NN * 128];     // relu(layer1) output

// ---------------- tf32 helpers ---------------------------------------------
__device__ __forceinline__ uint32_t f2tf(float f) {
    uint32_t u;
    asm("cvt.rna.tf32.f32 %0, %1;" : "=r"(u) : "f"(f));
    return u;
}

__device__ __forceinline__ void mma_tf32(float& c0, float& c1, float& c2, float& c3,
                                         uint32_t a0, uint32_t a1, uint32_t a2, uint32_t a3,
                                         uint32_t b0, uint32_t b1) {
    asm volatile(
        "mma.sync.aligned.m16n8k8.row.col.f32.tf32.tf32.f32 "
        "{%0,%1,%2,%3}, {%4,%5,%6,%7}, {%8,%9}, {%0,%1,%2,%3};\n"
        : "+f"(c0), "+f"(c1), "+f"(c2), "+f"(c3)
        : "r"(a0), "r"(a1), "r"(a2), "r"(a3), "r"(b0), "r"(b1));
}

// ---------------- edge dtype probe -----------------------------------------
// JAX with x64 disabled silently downcasts int64 -> int32, so the edge buffer
// may be either width. Probe once per launch.
__global__ void k_probe(const void* __restrict__ ei) {
    if (threadIdx.x == 0 && blockIdx.x == 0) {
        const long long* e64 = (const long long*)ei;
        int ok = 1;
        for (int i = 0; i < 1024; i++) {
            long long v = e64[i];
            if (v < 0 || v >= NN) { ok = 0; break; }
        }
        g_is64 = ok;
    }
}

__device__ __forceinline__ int edge_at(const void* ei, int idx) {
    if (g_is64) return (int)((const long long*)ei)[idx];
    return ((const int*)ei)[idx];
}

// ---------------- CSR build ------------------------------------------------
__global__ void k_zero_deg() {
    int i = blockIdx.x * 256 + threadIdx.x;
    if (i * 4 < NN) *(int4*)&g_deg[i * 4] = make_int4(0, 0, 0, 0);
}

__global__ void k_count_deg(const void* __restrict__ ei) {
    int e = blockIdx.x * 256 + threadIdx.x;
    if (e < NE) {
        int dst = edge_at(ei, NE + e);
        if ((unsigned)dst < NN) atomicAdd(&g_deg[dst], 1);
    }
}

__global__ void k_partial() {
    __shared__ int wsum[8];
    int b = blockIdx.x, tid = threadIdx.x;
    int idx = b * 1024 + tid * 4;
    int s = 0;
    if (idx < NN) {
        int4 d = *(const int4*)&g_deg[idx];
        s = ((idx + 0 < NN) ? d.x : 0) + ((idx + 1 < NN) ? d.y : 0) +
            ((idx + 2 < NN) ? d.z : 0) + ((idx + 3 < NN) ? d.w : 0);
    }
    int lane = tid & 31, wid = tid >> 5;
#pragma unroll
    for (int off = 16; off > 0; off >>= 1) s += __shfl_down_sync(0xffffffffu, s, off);
    if (lane == 0) wsum[wid] = s;
    __syncthreads();
    if (tid == 0) {
        int t = 0;
#pragma unroll
        for (int i = 0; i < 8; i++) t += wsum[i];
        g_bsum[b] = t;
    }
}

__global__ void k_scan_top() {
    __shared__ int ws[4];
    int tid = threadIdx.x;                   // 128 threads
    int v = (tid < NBLK) ? g_bsum[tid] : 0;
    int lane = tid & 31, wid = tid >> 5;
    int incl = v;
#pragma unroll
    for (int off = 1; off < 32; off <<= 1) {
        int n = __shfl_up_sync(0xffffffffu, incl, off);
        if (lane >= off) incl += n;
    }
    if (lane == 31) ws[wid] = incl;
    __syncthreads();
    if (tid < 4) {
        int t = ws[tid];
#pragma unroll
        for (int off = 1; off < 4; off <<= 1) {
            int n = __shfl_up_sync(0xfu, t, off);
            if (tid >= off) t += n;
        }
        ws[tid] = t;
    }
    __syncthreads();
    int excl = incl - v + ((wid > 0) ? ws[wid - 1] : 0);
    if (tid < NBLK) g_boff[tid] = excl;
    if (tid == NBLK - 1) g_rowptr[NN] = excl + v;
}

__global__ void k_rowptr() {
    __shared__ int wsum[8];
    int b = blockIdx.x, tid = threadIdx.x;
    int idx = b * 1024 + tid * 4;
    int d0 = 0, d1 = 0, d2 = 0, d3 = 0;
    if (idx < NN) {
        int4 d = *(const int4*)&g_deg[idx];
        d0 = (idx + 0 < NN) ? d.x : 0;
        d1 = (idx + 1 < NN) ? d.y : 0;
        d2 = (idx + 2 < NN) ? d.z : 0;
        d3 = (idx + 3 < NN) ? d.w : 0;
    }
    int s = d0 + d1 + d2 + d3;
    int lane = tid & 31, wid = tid >> 5;
    int incl = s;
#pragma unroll
    for (int off = 1; off < 32; off <<= 1) {
        int n = __shfl_up_sync(0xffffffffu, incl, off);
        if (lane >= off) incl += n;
    }
    if (lane == 31) wsum[wid] = incl;
    __syncthreads();
    if (tid < 8) {
        int t = wsum[tid];
#pragma unroll
        for (int off = 1; off < 8; off <<= 1) {
            int n = __shfl_up_sync(0xffu, t, off);
            if (tid >= off) t += n;
        }
        wsum[tid] = t;
    }
    __syncthreads();
    int run = incl - s + ((wid > 0) ? wsum[wid - 1] : 0) + g_boff[b];
    if (idx + 0 < NN) { g_rowptr[idx + 0] = run; g_cursor[idx + 0] = run; run += d0; }
    if (idx + 1 < NN) { g_rowptr[idx + 1] = run; g_cursor[idx + 1] = run; run += d1; }
    if (idx + 2 < NN) { g_rowptr[idx + 2] = run; g_cursor[idx + 2] = run; run += d2; }
    if (idx + 3 < NN) { g_rowptr[idx + 3] = run; g_cursor[idx + 3] = run; run += d3; }
}

__global__ void k_scatter(const void* __restrict__ ei) {
    int e = blockIdx.x * 256 + threadIdx.x;
    if (e < NE) {
        int src = edge_at(ei, e);
        int dst = edge_at(ei, NE + e);
        if ((unsigned)dst < NN && (unsigned)src < NN) {
            int pos = atomicAdd(&g_cursor[dst], 1);
            if ((unsigned)pos < NE) g_csrsrc[pos] = src;
        }
    }
}

// ---------------- mean aggregation: one warp per node ----------------------
__device__ __forceinline__ void agg_body(const float* __restrict__ in,
                                         float* __restrict__ out) {
    int w = (blockIdx.x * blockDim.x + threadIdx.x) >> 5;
    int lane = threadIdx.x & 31;
    if (w >= NN) return;
    int s = g_rowptr[w], e = g_rowptr[w + 1];
    float4 acc = make_float4(0.f, 0.f, 0.f, 0.f);
    const float4* in4 = (const float4*)in;
    int i = s;
    for (; i + 1 < e; i += 2) {
        int s0 = g_csrsrc[i];
        int s1 = g_csrsrc[i + 1];
        float4 v0 = in4[(size_t)s0 * 32 + lane];
        float4 v1 = in4[(size_t)s1 * 32 + lane];
        acc.x += v0.x + v1.x;
        acc.y += v0.y + v1.y;
        acc.z += v0.z + v1.z;
        acc.w += v0.w + v1.w;
    }
    if (i < e) {
        int s0 = g_csrsrc[i];
        float4 v0 = in4[(size_t)s0 * 32 + lane];
        acc.x += v0.x; acc.y += v0.y; acc.z += v0.z; acc.w += v0.w;
    }
    float inv = (e > s) ? 1.0f / (float)(e - s) : 1.0f;
    acc.x *= inv; acc.y *= inv; acc.z *= inv; acc.w *= inv;
    ((float4*)out)[(size_t)w * 32 + lane] = acc;
}

__global__ void k_agg_x(const float* __restrict__ x) { agg_body(x, g_mean); }
__global__ void k_agg_h() { agg_body(g_h, g_mean); }

// ---------------- layer 1: h = relu([mean|x] @ [W1l|W1r]^T + b1) -----------
// BM=128, BN=128, BK=16, 256 threads (8 warps as 4x2 of 32x64).
// TF32 mma.sync m16n8k8; A smem [m][k] stride 20, B smem [k][n] stride 136.
#define SA_S 20
#define SB_S 136
__global__ __launch_bounds__(256) void k_gemm1(const float* __restrict__ x,
                                               const float* __restrict__ W1l,
                                               const float* __restrict__ b1,
                                               const float* __restrict__ W1r) {
    __shared__ uint32_t sA[128 * SA_S];
    __shared__ uint32_t sB[16 * SB_S];
    int tid = threadIdx.x;
    int rowbase = blockIdx.x * 128;
    int wid = tid >> 5, lane = tid & 31;
    int g = lane >> 2, t = lane & 3;
    int wm = wid >> 1, wn = wid & 1;          // 4x2 warp grid
    int mrow = wm * 32, ncol = wn * 64;

    float acc[2][8][4];
#pragma unroll
    for (int mt = 0; mt < 2; mt++)
#pragma unroll
        for (int nt = 0; nt < 8; nt++)
#pragma unroll
            for (int j = 0; j < 4; j++) acc[mt][nt][j] = 0.f;

    for (int step = 0; step < 16; step++) {
        int k0 = step * 16;
        const float* Asrc = (k0 < 128) ? g_mean : x;
        const float* Wsrc = (k0 < 128) ? W1l : W1r;
        int kb = k0 & 127;
        __syncthreads();
        // A tile: 128 rows x 16 k (tf32-converted at store)
#pragma unroll
        for (int q = tid; q < 512; q += 256) {
            int m = q >> 2, kq = (q & 3) * 4;
            float4 v = make_float4(0.f, 0.f, 0.f, 0.f);
            int row = rowbase + m;
            if (row < NN) v = *(const float4*)&Asrc[(size_t)row * 128 + kb + kq];
            sA[m * SA_S + kq + 0] = f2tf(v.x);
            sA[m * SA_S + kq + 1] = f2tf(v.y);
            sA[m * SA_S + kq + 2] = f2tf(v.z);
            sA[m * SA_S + kq + 3] = f2tf(v.w);
        }
        // B tile: 128 n-rows x 16 k -> [k][n]
#pragma unroll
        for (int q = tid; q < 512; q += 256) {
            int n = q >> 2, kq = (q & 3) * 4;
            float4 w = *(const float4*)&Wsrc[(size_t)n * 128 + kb + kq];
            sB[(kq + 0) * SB_S + n] = f2tf(w.x);
            sB[(kq + 1) * SB_S + n] = f2tf(w.y);
            sB[(kq + 2) * SB_S + n] = f2tf(w.z);
            sB[(kq + 3) * SB_S + n] = f2tf(w.w);
        }
        __syncthreads();
#pragma unroll
        for (int kk = 0; kk < 16; kk += 8) {
            uint32_t a[2][4];
#pragma unroll
            for (int mt = 0; mt < 2; mt++) {
                int r0 = mrow + 16 * mt + g;
                a[mt][0] = sA[(r0)     * SA_S + kk + t];
                a[mt][1] = sA[(r0 + 8) * SA_S + kk + t];
                a[mt][2] = sA[(r0)     * SA_S + kk + t + 4];
                a[mt][3] = sA[(r0 + 8) * SA_S + kk + t + 4];
            }
#pragma unroll
            for (int nt = 0; nt < 8; nt++) {
                int nc = ncol + 8 * nt + g;
                uint32_t b0 = sB[(kk + t)     * SB_S + nc];
                uint32_t b1r = sB[(kk + t + 4) * SB_S + nc];
#pragma unroll
                for (int mt = 0; mt < 2; mt++)
                    mma_tf32(acc[mt][nt][0], acc[mt][nt][1], acc[mt][nt][2], acc[mt][nt][3],
                             a[mt][0], a[mt][1], a[mt][2], a[mt][3], b0, b1r);
            }
        }
    }

    // epilogue: bias + relu -> g_h
#pragma unroll
    for (int nt = 0; nt < 8; nt++) {
        int cb = ncol + 8 * nt + 2 * t;
        float2 bias = *(const float2*)&b1[cb];
#pragma unroll
        for (int mt = 0; mt < 2; mt++) {
            int r0 = rowbase + mrow + 16 * mt + g;
            int r1 = r0 + 8;
            if (r0 < NN) {
                float2 o;
                o.x = fmaxf(acc[mt][nt][0] + bias.x, 0.f);
                o.y = fmaxf(acc[mt][nt][1] + bias.y, 0.f);
                *(float2*)&g_h[(size_t)r0 * 128 + cb] = o;
            }
            if (r1 < NN) {
                float2 o;
                o.x = fmaxf(acc[mt][nt][2] + bias.x, 0.f);
                o.y = fmaxf(acc[mt][nt][3] + bias.y, 0.f);
                *(float2*)&g_h[(size_t)r1 * 128 + cb] = o;
            }
        }
    }
}

// ---------------- layer 2 + log_softmax ------------------------------------
// BM=128, BN=64 (all classes), BK=16, 256 threads (8 warps as 4x2 of 32x32).
// smem reused: stage tiles (A stride 20, B stride 136) then C tile [128][65].
__global__ __launch_bounds__(256) void k_gemm2(const float* __restrict__ W2l,
                                               const float* __restrict__ b2,
                                               const float* __restrict__ W2r,
                                               float* __restrict__ out) {
    __shared__ float sbuf[128 * 65];   // 33.3KB; stage area needs 4736 floats
    __shared__ float sLZ[128];
    uint32_t* sA = (uint32_t*)sbuf;              // [128][20]
    uint32_t* sB = (uint32_t*)(sbuf + 128 * SA_S);  // [16][136]
    int tid = threadIdx.x;
    int rowbase = blockIdx.x * 128;
    int wid = tid >> 5, lane = tid & 31;
    int g = lane >> 2, t = lane & 3;
    int wm = wid >> 1, wn = wid & 1;
    int mrow = wm * 32, ncol = wn * 32;

    float acc[2][4][4];
#pragma unroll
    for (int mt = 0; mt < 2; mt++)
#pragma unroll
        for (int nt = 0; nt < 4; nt++)
#pragma unroll
            for (int j = 0; j < 4; j++) acc[mt][nt][j] = 0.f;

    for (int step = 0; step < 16; step++) {
        int k0 = step * 16;
        const float* Asrc = (k0 < 128) ? g_mean : g_h;
        const float* Wsrc = (k0 < 128) ? W2l : W2r;
        int kb = k0 & 127;
        __syncthreads();
#pragma unroll
        for (int q = tid; q < 512; q += 256) {
            int m = q >> 2, kq = (q & 3) * 4;
            float4 v = make_float4(0.f, 0.f, 0.f, 0.f);
            int row = rowbase + m;
            if (row < NN) v = *(const float4*)&Asrc[(size_t)row * 128 + kb + kq];
            sA[m * SA_S + kq + 0] = f2tf(v.x);
            sA[m * SA_S + kq + 1] = f2tf(v.y);
            sA[m * SA_S + kq + 2] = f2tf(v.z);
            sA[m * SA_S + kq + 3] = f2tf(v.w);
        }
        // B tile: 64 n-rows x 16 k = 256 float4 -> one per thread
        {
            int n = tid >> 2, kq = (tid & 3) * 4;
            float4 w = *(const float4*)&Wsrc[(size_t)n * 128 + kb + kq];
            sB[(kq + 0) * SB_S + n] = f2tf(w.x);
            sB[(kq + 1) * SB_S + n] = f2tf(w.y);
            sB[(kq + 2) * SB_S + n] = f2tf(w.z);
            sB[(kq + 3) * SB_S + n] = f2tf(w.w);
        }
        __syncthreads();
#pragma unroll
        for (int kk = 0; kk < 16; kk += 8) {
            uint32_t a[2][4];
#pragma unroll
            for (int mt = 0; mt < 2; mt++) {
                int r0 = mrow + 16 * mt + g;
                a[mt][0] = sA[(r0)     * SA_S + kk + t];
                a[mt][1] = sA[(r0 + 8) * SA_S + kk + t];
                a[mt][2] = sA[(r0)     * SA_S + kk + t + 4];
                a[mt][3] = sA[(r0 + 8) * SA_S + kk + t + 4];
            }
#pragma unroll
            for (int nt = 0; nt < 4; nt++) {
                int nc = ncol + 8 * nt + g;
                uint32_t b0 = sB[(kk + t)     * SB_S + nc];
                uint32_t b1r = sB[(kk + t + 4) * SB_S + nc];
#pragma unroll
                for (int mt = 0; mt < 2; mt++)
                    mma_tf32(acc[mt][nt][0], acc[mt][nt][1], acc[mt][nt][2], acc[mt][nt][3],
                             a[mt][0], a[mt][1], a[mt][2], a[mt][3], b0, b1r);
            }
        }
    }
    __syncthreads();  // done with stage tiles; reuse sbuf as C

    float (*sC)[65] = (float (*)[65])sbuf;  // [128][65]
#pragma unroll
    for (int nt = 0; nt < 4; nt++) {
        int cb = ncol + 8 * nt + 2 * t;
        float2 bias = *(const float2*)&b2[cb];
#pragma unroll
        for (int mt = 0; mt < 2; mt++) {
            int r0 = mrow + 16 * mt + g;
            sC[r0][cb]         = acc[mt][nt][0] + bias.x;
            sC[r0][cb + 1]     = acc[mt][nt][1] + bias.y;
            sC[r0 + 8][cb]     = acc[mt][nt][2] + bias.x;
            sC[r0 + 8][cb + 1] = acc[mt][nt][3] + bias.y;
        }
    }
    __syncthreads();

    if (tid < 128) {
        float m = -INFINITY;
#pragma unroll
        for (int c = 0; c < 64; c++) m = fmaxf(m, sC[tid][c]);
        float s = 0.f;
#pragma unroll
        for (int c = 0; c < 64; c++) s += __expf(sC[tid][c] - m);
        sLZ[tid] = m + __logf(s);
    }
    __syncthreads();

#pragma unroll
    for (int q = tid; q < 8192; q += 256) {
        int r = q >> 6, c = q & 63;
        int row = rowbase + r;
        if (row < NN) out[(size_t)row * 64 + c] = sC[r][c] - sLZ[r];
    }
}

// ---------------- launch ---------------------------------------------------
extern "C" void kernel_launch(void* const* d_in, const int* in_sizes, int n_in,
                              void* d_out, int out_size) {
    const float* x   = (const float*)d_in[0];
    const void*  ei  = d_in[1];
    const float* W1l = (const float*)d_in[2];
    const float* b1  = (const float*)d_in[3];
    const float* W1r = (const float*)d_in[4];
    const float* W2l = (const float*)d_in[5];
    const float* b2  = (const float*)d_in[6];
    const float* W2r = (const float*)d_in[7];
    float* out = (float*)d_out;
    (void)in_sizes; (void)n_in; (void)out_size;

    // edge dtype probe + CSR build (parallel 3-stage scan)
    k_probe<<<1, 32>>>(ei);
    k_zero_deg<<<(NN / 4 + 255) / 256, 256>>>();
    k_count_deg<<<(NE + 255) / 256, 256>>>(ei);
    k_partial<<<NBLK, 256>>>();
    k_scan_top<<<1, 128>>>();
    k_rowptr<<<NBLK, 256>>>();
    k_scatter<<<(NE + 255) / 256, 256>>>(ei);

    // layer 1
    k_agg_x<<<12500, 256>>>(x);                           // mean1 -> g_mean
    k_gemm1<<<(NN + 127) / 128, 256>>>(x, W1l, b1, W1r);  // -> g_h

    // layer 2
    k_agg_h<<<12500, 256>>>();                            // mean2 -> g_mean
    k_gemm2<<<(NN + 127) / 128, 256>>>(W2l, b2, W2r, out);
}

// round 12
// speedup vs baseline: 2.4404x; 1.6636x over previous
// R8: full bf16 data plane (agg gathers + m16n8k16 bf16 mma), fp32 accumulate
#include <cuda_runtime.h>
#include <cuda_bf16.h>
#include <math.h>
#include <stdint.h>

#define NN 100000
#define NE 1600000
#define NBLK 98            // ceil(NN / 1024)

// ---------------- scratch (device globals: no runtime allocation) ----------
__device__ int   g_is64;
__device__ int   g_deg[NN + 4];
__device__ int   g_rowptr[NN + 1];
__device__ int   g_cursor[NN];
__device__ int   g_csrsrc[NE];
__device__ int   g_bsum[NBLK];
__device__ int   g_boff[NBLK];
__device__ __nv_bfloat16 g_xbf[(size_t)NN * 128];    // x in bf16
__device__ __nv_bfloat16 g_hbf[(size_t)NN * 128];    // relu(layer1) in bf16
__device__ __nv_bfloat16 g_meanbf[(size_t)NN * 128]; // mean1 then mean2, bf16

// ---------------- helpers ---------------------------------------------------
__device__ __forceinline__ uint32_t f2bf2(float lo, float hi) {
    __nv_bfloat162 h = __floats2bfloat162_rn(lo, hi);
    return *(uint32_t*)&h;
}

__device__ __forceinline__ void mma_bf16(float& c0, float& c1, float& c2, float& c3,
                                         uint32_t a0, uint32_t a1, uint32_t a2, uint32_t a3,
                                         uint32_t b0, uint32_t b1) {
    asm volatile(
        "mma.sync.aligned.m16n8k16.row.col.f32.bf16.bf16.f32 "
        "{%0,%1,%2,%3}, {%4,%5,%6,%7}, {%8,%9}, {%0,%1,%2,%3};\n"
        : "+f"(c0), "+f"(c1), "+f"(c2), "+f"(c3)
        : "r"(a0), "r"(a1), "r"(a2), "r"(a3), "r"(b0), "r"(b1));
}

// ---------------- edge dtype probe -----------------------------------------
// JAX x64-disabled silently downcasts int64 edges to int32; probe which width.
__global__ void k_probe(const void* __restrict__ ei) {
    if (threadIdx.x == 0 && blockIdx.x == 0) {
        const long long* e64 = (const long long*)ei;
        int ok = 1;
        for (int i = 0; i < 1024; i++) {
            long long v = e64[i];
            if (v < 0 || v >= NN) { ok = 0; break; }
        }
        g_is64 = ok;
    }
}

__device__ __forceinline__ int edge_at(const void* ei, int idx) {
    if (g_is64) return (int)((const long long*)ei)[idx];
    return ((const int*)ei)[idx];
}

// ---------------- CSR build ------------------------------------------------
__global__ void k_zero_deg() {
    int i = blockIdx.x * 256 + threadIdx.x;
    if (i * 4 < NN) *(int4*)&g_deg[i * 4] = make_int4(0, 0, 0, 0);
}

__global__ void k_count_deg(const void* __restrict__ ei) {
    int e = blockIdx.x * 256 + threadIdx.x;
    if (e < NE) {
        int dst = edge_at(ei, NE + e);
        if ((unsigned)dst < NN) atomicAdd(&g_deg[dst], 1);
    }
}

__global__ void k_partial() {
    __shared__ int wsum[8];
    int b = blockIdx.x, tid = threadIdx.x;
    int idx = b * 1024 + tid * 4;
    int s = 0;
    if (idx < NN) {
        int4 d = *(const int4*)&g_deg[idx];
        s = ((idx + 0 < NN) ? d.x : 0) + ((idx + 1 < NN) ? d.y : 0) +
            ((idx + 2 < NN) ? d.z : 0) + ((idx + 3 < NN) ? d.w : 0);
    }
    int lane = tid & 31, wid = tid >> 5;
#pragma unroll
    for (int off = 16; off > 0; off >>= 1) s += __shfl_down_sync(0xffffffffu, s, off);
    if (lane == 0) wsum[wid] = s;
    __syncthreads();
    if (tid == 0) {
        int t = 0;
#pragma unroll
        for (int i = 0; i < 8; i++) t += wsum[i];
        g_bsum[b] = t;
    }
}

__global__ void k_scan_top() {
    __shared__ int ws[4];
    int tid = threadIdx.x;                   // 128 threads
    int v = (tid < NBLK) ? g_bsum[tid] : 0;
    int lane = tid & 31, wid = tid >> 5;
    int incl = v;
#pragma unroll
    for (int off = 1; off < 32; off <<= 1) {
        int n = __shfl_up_sync(0xffffffffu, incl, off);
        if (lane >= off) incl += n;
    }
    if (lane == 31) ws[wid] = incl;
    __syncthreads();
    if (tid < 4) {
        int t = ws[tid];
#pragma unroll
        for (int off = 1; off < 4; off <<= 1) {
            int n = __shfl_up_sync(0xfu, t, off);
            if (tid >= off) t += n;
        }
        ws[tid] = t;
    }
    __syncthreads();
    int excl = incl - v + ((wid > 0) ? ws[wid - 1] : 0);
    if (tid < NBLK) g_boff[tid] = excl;
    if (tid == NBLK - 1) g_rowptr[NN] = excl + v;
}

__global__ void k_rowptr() {
    __shared__ int wsum[8];
    int b = blockIdx.x, tid = threadIdx.x;
    int idx = b * 1024 + tid * 4;
    int d0 = 0, d1 = 0, d2 = 0, d3 = 0;
    if (idx < NN) {
        int4 d = *(const int4*)&g_deg[idx];
        d0 = (idx + 0 < NN) ? d.x : 0;
        d1 = (idx + 1 < NN) ? d.y : 0;
        d2 = (idx + 2 < NN) ? d.z : 0;
        d3 = (idx + 3 < NN) ? d.w : 0;
    }
    int s = d0 + d1 + d2 + d3;
    int lane = tid & 31, wid = tid >> 5;
    int incl = s;
#pragma unroll
    for (int off = 1; off < 32; off <<= 1) {
        int n = __shfl_up_sync(0xffffffffu, incl, off);
        if (lane >= off) incl += n;
    }
    if (lane == 31) wsum[wid] = incl;
    __syncthreads();
    if (tid < 8) {
        int t = wsum[tid];
#pragma unroll
        for (int off = 1; off < 8; off <<= 1) {
            int n = __shfl_up_sync(0xffu, t, off);
            if (tid >= off) t += n;
        }
        wsum[tid] = t;
    }
    __syncthreads();
    int run = incl - s + ((wid > 0) ? wsum[wid - 1] : 0) + g_boff[b];
    if (idx + 0 < NN) { g_rowptr[idx + 0] = run; g_cursor[idx + 0] = run; run += d0; }
    if (idx + 1 < NN) { g_rowptr[idx + 1] = run; g_cursor[idx + 1] = run; run += d1; }
    if (idx + 2 < NN) { g_rowptr[idx + 2] = run; g_cursor[idx + 2] = run; run += d2; }
    if (idx + 3 < NN) { g_rowptr[idx + 3] = run; g_cursor[idx + 3] = run; run += d3; }
}

__global__ void k_scatter(const void* __restrict__ ei) {
    int e = blockIdx.x * 256 + threadIdx.x;
    if (e < NE) {
        int src = edge_at(ei, e);
        int dst = edge_at(ei, NE + e);
        if ((unsigned)dst < NN && (unsigned)src < NN) {
            int pos = atomicAdd(&g_cursor[dst], 1);
            if ((unsigned)pos < NE) g_csrsrc[pos] = src;
        }
    }
}

// ---------------- x -> bf16 conversion -------------------------------------
__global__ void k_cvt_x(const float* __restrict__ x) {
    int i = blockIdx.x * 256 + threadIdx.x;   // one per 4 floats; NN*32 total
    if (i < NN * 32) {
        float4 v = *(const float4*)&x[(size_t)i * 4];
        uint2 o;
        o.x = f2bf2(v.x, v.y);
        o.y = f2bf2(v.z, v.w);
        *(uint2*)&g_xbf[(size_t)i * 4] = o;
    }
}

// ---------------- mean aggregation: one warp per node, bf16 rows -----------
// Each lane covers 4 bf16 (one uint2); a row is 32 uint2 = 256B, coalesced.
__device__ __forceinline__ void agg_body(const __nv_bfloat16* __restrict__ in,
                                         __nv_bfloat16* __restrict__ out) {
    int w = (blockIdx.x * blockDim.x + threadIdx.x) >> 5;
    int lane = threadIdx.x & 31;
    if (w >= NN) return;
    int s = g_rowptr[w], e = g_rowptr[w + 1];
    float4 acc = make_float4(0.f, 0.f, 0.f, 0.f);
    const uint2* in2 = (const uint2*)in;
    int i = s;
    for (; i + 1 < e; i += 2) {
        int s0 = g_csrsrc[i];
        int s1 = g_csrsrc[i + 1];
        uint2 u0 = in2[(size_t)s0 * 32 + lane];
        uint2 u1 = in2[(size_t)s1 * 32 + lane];
        float2 a0 = __bfloat1622float2(*(__nv_bfloat162*)&u0.x);
        float2 a1 = __bfloat1622float2(*(__nv_bfloat162*)&u0.y);
        float2 b0 = __bfloat1622float2(*(__nv_bfloat162*)&u1.x);
        float2 b1 = __bfloat1622float2(*(__nv_bfloat162*)&u1.y);
        acc.x += a0.x + b0.x;
        acc.y += a0.y + b0.y;
        acc.z += a1.x + b1.x;
        acc.w += a1.y + b1.y;
    }
    if (i < e) {
        int s0 = g_csrsrc[i];
        uint2 u0 = in2[(size_t)s0 * 32 + lane];
        float2 a0 = __bfloat1622float2(*(__nv_bfloat162*)&u0.x);
        float2 a1 = __bfloat1622float2(*(__nv_bfloat162*)&u0.y);
        acc.x += a0.x; acc.y += a0.y; acc.z += a1.x; acc.w += a1.y;
    }
    float inv = (e > s) ? 1.0f / (float)(e - s) : 1.0f;
    uint2 o;
    o.x = f2bf2(acc.x * inv, acc.y * inv);
    o.y = f2bf2(acc.z * inv, acc.w * inv);
    ((uint2*)out)[(size_t)w * 32 + lane] = o;
}

__global__ void k_agg_x() { agg_body(g_xbf, g_meanbf); }
__global__ void k_agg_h() { agg_body(g_hbf, g_meanbf); }

// ---------------- layer 1: h = relu([mean|x] @ [W1l|W1r]^T + b1) -----------
// BM=128, BN=128, BK=16, 256 threads (8 warps as 4x2 of 32x64 tiles).
// bf16 mma m16n8k16; A smem [m][k/2] uint32 stride 12; B smem [k/2][n] stride 136.
#define SA_S 12
#define SB_S 136
__global__ __launch_bounds__(256) void k_gemm1(const float* __restrict__ W1l,
                                               const float* __restrict__ b1,
                                               const float* __restrict__ W1r) {
    __shared__ uint32_t sA[128 * SA_S];   // 6KB
    __shared__ uint32_t sB[8 * SB_S];     // 4.25KB
    int tid = threadIdx.x;
    int rowbase = blockIdx.x * 128;
    int wid = tid >> 5, lane = tid & 31;
    int g = lane >> 2, t = lane & 3;
    int wm = wid >> 1, wn = wid & 1;
    int mrow = wm * 32, ncol = wn * 64;

    float acc[2][8][4];
#pragma unroll
    for (int mt = 0; mt < 2; mt++)
#pragma unroll
        for (int nt = 0; nt < 8; nt++)
#pragma unroll
            for (int j = 0; j < 4; j++) acc[mt][nt][j] = 0.f;

    for (int step = 0; step < 16; step++) {
        const __nv_bfloat16* Asrc = (step < 8) ? g_meanbf : g_xbf;
        const float* Wsrc = (step < 8) ? W1l : W1r;
        int kb = (step & 7) * 16;
        __syncthreads();
        // A tile: 128 rows x 16 k (bf16 direct copy, no conversion)
#pragma unroll
        for (int q = tid; q < 512; q += 256) {
            int m = q >> 2, kq = (q & 3) * 4;
            uint2 v = make_uint2(0, 0);
            int row = rowbase + m;
            if (row < NN) v = *(const uint2*)&Asrc[(size_t)row * 128 + kb + kq];
            sA[m * SA_S + (kq >> 1)]     = v.x;
            sA[m * SA_S + (kq >> 1) + 1] = v.y;
        }
        // B tile: 128 n-rows x 16 k (fp32 -> bf16 at store)
#pragma unroll
        for (int q = tid; q < 512; q += 256) {
            int n = q >> 2, kq = (q & 3) * 4;
            float4 w = *(const float4*)&Wsrc[(size_t)n * 128 + kb + kq];
            sB[(kq >> 1) * SB_S + n]       = f2bf2(w.x, w.y);
            sB[((kq >> 1) + 1) * SB_S + n] = f2bf2(w.z, w.w);
        }
        __syncthreads();
        // one m16n8k16 mma per (mt, nt) covers the whole BK=16
        uint32_t a[2][4];
#pragma unroll
        for (int mt = 0; mt < 2; mt++) {
            int r0 = mrow + 16 * mt + g;
            a[mt][0] = sA[(r0)     * SA_S + t];
            a[mt][1] = sA[(r0 + 8) * SA_S + t];
            a[mt][2] = sA[(r0)     * SA_S + t + 4];
            a[mt][3] = sA[(r0 + 8) * SA_S + t + 4];
        }
#pragma unroll
        for (int nt = 0; nt < 8; nt++) {
            int nc = ncol + 8 * nt + g;
            uint32_t b0 = sB[(t)     * SB_S + nc];
            uint32_t b1 = sB[(t + 4) * SB_S + nc];
#pragma unroll
            for (int mt = 0; mt < 2; mt++)
                mma_bf16(acc[mt][nt][0], acc[mt][nt][1], acc[mt][nt][2], acc[mt][nt][3],
                         a[mt][0], a[mt][1], a[mt][2], a[mt][3], b0, b1);
        }
    }

    // epilogue: bias + relu -> g_hbf (bf16 pairs)
#pragma unroll
    for (int nt = 0; nt < 8; nt++) {
        int cb = ncol + 8 * nt + 2 * t;
        float2 bias = *(const float2*)&b1[cb];
#pragma unroll
        for (int mt = 0; mt < 2; mt++) {
            int r0 = rowbase + mrow + 16 * mt + g;
            int r1 = r0 + 8;
            if (r0 < NN)
                *(uint32_t*)&g_hbf[(size_t)r0 * 128 + cb] =
                    f2bf2(fmaxf(acc[mt][nt][0] + bias.x, 0.f),
                          fmaxf(acc[mt][nt][1] + bias.y, 0.f));
            if (r1 < NN)
                *(uint32_t*)&g_hbf[(size_t)r1 * 128 + cb] =
                    f2bf2(fmaxf(acc[mt][nt][2] + bias.x, 0.f),
                          fmaxf(acc[mt][nt][3] + bias.y, 0.f));
        }
    }
}

// ---------------- layer 2 + log_softmax ------------------------------------
// BM=128, BN=64 (all classes), BK=16, 256 threads (8 warps as 4x2 of 32x32).
__global__ __launch_bounds__(256) void k_gemm2(const float* __restrict__ W2l,
                                               const float* __restrict__ b2,
                                               const float* __restrict__ W2r,
                                               float* __restrict__ out) {
    __shared__ uint32_t sA[128 * SA_S];   // 6KB
    __shared__ uint32_t sB[8 * SB_S];     // 4.25KB
    __shared__ float sC[128][65];         // 33.3KB
    __shared__ float sLZ[128];
    int tid = threadIdx.x;
    int rowbase = blockIdx.x * 128;
    int wid = tid >> 5, lane = tid & 31;
    int g = lane >> 2, t = lane & 3;
    int wm = wid >> 1, wn = wid & 1;
    int mrow = wm * 32, ncol = wn * 32;

    float acc[2][4][4];
#pragma unroll
    for (int mt = 0; mt < 2; mt++)
#pragma unroll
        for (int nt = 0; nt < 4; nt++)
#pragma unroll
            for (int j = 0; j < 4; j++) acc[mt][nt][j] = 0.f;

    for (int step = 0; step < 16; step++) {
        const __nv_bfloat16* Asrc = (step < 8) ? g_meanbf : g_hbf;
        const float* Wsrc = (step < 8) ? W2l : W2r;
        int kb = (step & 7) * 16;
        __syncthreads();
#pragma unroll
        for (int q = tid; q < 512; q += 256) {
            int m = q >> 2, kq = (q & 3) * 4;
            uint2 v = make_uint2(0, 0);
            int row = rowbase + m;
            if (row < NN) v = *(const uint2*)&Asrc[(size_t)row * 128 + kb + kq];
            sA[m * SA_S + (kq >> 1)]     = v.x;
            sA[m * SA_S + (kq >> 1) + 1] = v.y;
        }
        // B tile: 64 n-rows x 16 k = 256 float4 -> one per thread
        {
            int n = tid >> 2, kq = (tid & 3) * 4;
            float4 w = *(const float4*)&Wsrc[(size_t)n * 128 + kb + kq];
            sB[(kq >> 1) * SB_S + n]       = f2bf2(w.x, w.y);
            sB[((kq >> 1) + 1) * SB_S + n] = f2bf2(w.z, w.w);
        }
        __syncthreads();
        uint32_t a[2][4];
#pragma unroll
        for (int mt = 0; mt < 2; mt++) {
            int r0 = mrow + 16 * mt + g;
            a[mt][0] = sA[(r0)     * SA_S + t];
            a[mt][1] = sA[(r0 + 8) * SA_S + t];
            a[mt][2] = sA[(r0)     * SA_S + t + 4];
            a[mt][3] = sA[(r0 + 8) * SA_S + t + 4];
        }
#pragma unroll
        for (int nt = 0; nt < 4; nt++) {
            int nc = ncol + 8 * nt + g;
            uint32_t b0 = sB[(t)     * SB_S + nc];
            uint32_t b1 = sB[(t + 4) * SB_S + nc];
#pragma unroll
            for (int mt = 0; mt < 2; mt++)
                mma_bf16(acc[mt][nt][0], acc[mt][nt][1], acc[mt][nt][2], acc[mt][nt][3],
                         a[mt][0], a[mt][1], a[mt][2], a[mt][3], b0, b1);
        }
    }

    // epilogue: bias into fp32 C tile, then fused log_softmax
#pragma unroll
    for (int nt = 0; nt < 4; nt++) {
        int cb = ncol + 8 * nt + 2 * t;
        float2 bias = *(const float2*)&b2[cb];
#pragma unroll
        for (int mt = 0; mt < 2; mt++) {
            int r0 = mrow + 16 * mt + g;
            sC[r0][cb]         = acc[mt][nt][0] + bias.x;
            sC[r0][cb + 1]     = acc[mt][nt][1] + bias.y;
            sC[r0 + 8][cb]     = acc[mt][nt][2] + bias.x;
            sC[r0 + 8][cb + 1] = acc[mt][nt][3] + bias.y;
        }
    }
    __syncthreads();

    if (tid < 128) {
        float m = -INFINITY;
#pragma unroll
        for (int c = 0; c < 64; c++) m = fmaxf(m, sC[tid][c]);
        float s = 0.f;
#pragma unroll
        for (int c = 0; c < 64; c++) s += __expf(sC[tid][c] - m);
        sLZ[tid] = m + __logf(s);
    }
    __syncthreads();

#pragma unroll
    for (int q = tid; q < 8192; q += 256) {
        int r = q >> 6, c = q & 63;
        int row = rowbase + r;
        if (row < NN) out[(size_t)row * 64 + c] = sC[r][c] - sLZ[r];
    }
}

// ---------------- launch ---------------------------------------------------
extern "C" void kernel_launch(void* const* d_in, const int* in_sizes, int n_in,
                              void* d_out, int out_size) {
    const float* x   = (const float*)d_in[0];
    const void*  ei  = d_in[1];
    const float* W1l = (const float*)d_in[2];
    const float* b1  = (const float*)d_in[3];
    const float* W1r = (const float*)d_in[4];
    const float* W2l = (const float*)d_in[5];
    const float* b2  = (const float*)d_in[6];
    const float* W2r = (const float*)d_in[7];
    float* out = (float*)d_out;
    (void)in_sizes; (void)n_in; (void)out_size;

    // edge dtype probe + CSR build (parallel 3-stage scan) + x conversion
    k_probe<<<1, 32>>>(ei);
    k_zero_deg<<<(NN / 4 + 255) / 256, 256>>>();
    k_count_deg<<<(NE + 255) / 256, 256>>>(ei);
    k_partial<<<NBLK, 256>>>();
    k_scan_top<<<1, 128>>>();
    k_rowptr<<<NBLK, 256>>>();
    k_scatter<<<(NE + 255) / 256, 256>>>(ei);
    k_cvt_x<<<12500, 256>>>(x);

    // layer 1
    k_agg_x<<<12500, 256>>>();                       // mean1 -> g_meanbf
    k_gemm1<<<(NN + 127) / 128, 256>>>(W1l, b1, W1r);  // -> g_hbf

    // layer 2
    k_agg_h<<<12500, 256>>>();                       // mean2 -> g_meanbf
    k_gemm2<<<(NN + 127) / 128, 256>>>(W2l, b2, W2r, out);
}